// round 11
// baseline (speedup 1.0000x reference)
#include <cuda_runtime.h>
#include <math.h>

#define KNOTS   1024
#define S_PTS   4095
#define INV_SAMP (1.0f / 4096.0f)
#define INV_S    (1.0f / (float)S_PTS)
#define NMOM   6            // Taylor n = 0..5 (gate 0.1 -> err <= 1.4e-9/knot)
#define GATE   0.1f
#define NBLK   4
#define NTHR   1024
#define NWARP  (NTHR / 32)
#define TGUARD 13.3f        // conservative: e<88 <=> |a|<13.2665

// ---------------- scratch (device globals; slow path only) -------------------
__device__ float g_smear[(size_t)KNOTS * S_PTS];
__device__ float g_rowsum[KNOTS], g_coef1[KNOTS];
__device__ float g_cwp[NBLK * KNOTS];
__device__ float g_Rp[NBLK];
__device__ unsigned g_count = 0;   // self-resetting per barrier episode
__device__ unsigned g_gen   = 0;   // monotone across graph replays

// ---------------- warp helpers -------------------------------------------------
__device__ __forceinline__ float warp_sum(float v) {
    #pragma unroll
    for (int o = 16; o > 0; o >>= 1) v += __shfl_xor_sync(0xFFFFFFFFu, v, o);
    return v;
}
__device__ __forceinline__ float warp_max(float v) {
    #pragma unroll
    for (int o = 16; o > 0; o >>= 1) v = fmaxf(v, __shfl_xor_sync(0xFFFFFFFFu, v, o));
    return v;
}
__device__ __forceinline__ float warp_min(float v) {
    #pragma unroll
    for (int o = 16; o > 0; o >>= 1) v = fminf(v, __shfl_xor_sync(0xFFFFFFFFu, v, o));
    return v;
}
// broadcast block sum for the slow path (1024 threads = 32 warps)
__device__ __forceinline__ float block_sum_b(float v, float* red) {
    int tid = threadIdx.x;
    v = warp_sum(v);
    if ((tid & 31) == 0) red[tid >> 5] = v;
    __syncthreads();
    if (tid == 0) {
        float r = red[0];
        #pragma unroll
        for (int w = 1; w < NWARP; w++) r += red[w];
        red[NWARP] = r;
    }
    __syncthreads();
    float o = red[NWARP];
    __syncthreads();
    return o;
}

// conservative upper bound of exp(t): 1+t+t^2 for t<=1 (valid for all t<=1),
// inflated __expf otherwise. NaN propagates -> comparisons fail -> slow path.
__device__ __forceinline__ float exp_ub(float t) {
    return (t <= 1.0f) ? fmaf(t, t + 1.0f, 1.0f) : __expf(t) * 1.01f;
}

// ---------------- software grid barrier (slow path only) ---------------------
__device__ __forceinline__ void grid_barrier() {
    __threadfence();
    __syncthreads();
    if (threadIdx.x == 0) {
        unsigned my = *((volatile unsigned*)&g_gen);
        if (atomicAdd(&g_count, 1u) == NBLK - 1) {
            g_count = 0;
            __threadfence();
            *((volatile unsigned*)&g_gen) = my + 1;
        } else {
            while (*((volatile unsigned*)&g_gen) == my) { }
        }
        __threadfence();
    }
    __syncthreads();
}

// ======================= the single kernel ====================================
__global__ __launch_bounds__(NTHR, 1)
void knot_one(const float* __restrict__ x,
              const float* __restrict__ sw,
              const float* __restrict__ kmean,
              const float* __restrict__ klow,
              const float* __restrict__ khigh,
              const float* __restrict__ emean,
              const float* __restrict__ elow,
              const float* __restrict__ ehigh,
              const float* __restrict__ pol,
              float* __restrict__ out) {
    // pool aliased per phase:
    //   fast reduce:  buf[14 * 1024]         (56 KB)
    //   slow mix:     9 arrays x 1024        (36 KB)
    //   slow output:  6 arrays x 1024        (24 KB)
    __shared__ float pool[14 * 1024];
    __shared__ float red[NWARP + 1];
    __shared__ float s_res[16];
    __shared__ float s_cf[2 * NMOM];
    __shared__ int   s_fastenv;

    const int tid  = threadIdx.x;
    const int bid  = blockIdx.x;
    const int warp = tid >> 5, lane = tid & 31;

    // =============== phase 1: one knot/thread, 4 MUFU =========================
    const float2 swv  = *(const float2*)sw;
    const float lower = swv.x, upper = swv.y;
    const float xk   = x[tid];
    const float kml  = klow[tid];
    const float kmh  = khigh[tid];
    const float mean = kmean[tid];
    const float em   = emean[tid];
    const float eln  = elow[tid];
    const float ehn  = ehigh[tid];

    const float xlow  = (1.0f - lower) * xk;
    const float xstep = ((upper - lower) * xk) * INV_SAMP;
    const int   cst   = (xstep == 0.0f) ? 1 : 0;
    const float d     = xlow - mean;
    const float r0    = __expf(-((xlow <= mean) ? kml : kmh));   // MUFU 1
    const float a0    = d * r0;
    const float v0    = __expf(-0.5f * a0 * a0);                  // MUFU 2
    const float B     = (float)S_PTS * v0;
    const float v0c   = cst ? v0 : 0.0f;
    const int noncst  = cst ? 0 : 1;

    const float highs = (1.0f + upper) * xk;
    const float erlw  = __expf(-xlow);                            // MUFU 3
    const float erhg  = __expf(-highs);                           // MUFU 4
    const float hlo = xk * erlw, hhi = xk * erhg;
    const float clo = 0.5f * hlo * hlo;
    const float chi = 0.5f * hhi * hhi;

    // =============== phase 2: single batched 14-quantity reduction ===========
    // q 0..4 : low moments n=1..5 | q 5..9 : high moments | q10: v0 sum
    // q11: cmax (max) | q12: Bmin (min) | q13: Bmax (max)
    {
        float* buf = pool;
        float pl = clo, ph = chi;
        #pragma unroll
        for (int n = 1; n <= 5; n++) {
            buf[(n - 1) * NTHR + tid] = pl;
            buf[(4 + n) * NTHR + tid] = ph;
            pl *= clo; ph *= chi;
        }
        buf[10 * NTHR + tid] = v0c;
        buf[11 * NTHR + tid] = fmaxf(clo, chi);
        buf[12 * NTHR + tid] = B;
        buf[13 * NTHR + tid] = B;
    }
    int anyvar = __syncthreads_or(noncst);   // barrier #1 (covers buf writes)

    if (warp < 14) {
        const float* b = pool + warp * NTHR;
        float acc[32];
        #pragma unroll
        for (int i = 0; i < 32; i++) acc[i] = b[lane + 32 * i];
        float v;
        if (warp == 11 || warp == 13) {       // max
            v = acc[0];
            #pragma unroll
            for (int i = 1; i < 32; i++) v = fmaxf(v, acc[i]);
            v = warp_max(v);
        } else if (warp == 12) {              // min
            v = acc[0];
            #pragma unroll
            for (int i = 1; i < 32; i++) v = fminf(v, acc[i]);
            v = warp_min(v);
        } else {                              // sum
            v = 0.0f;
            #pragma unroll
            for (int i = 0; i < 32; i++) v += acc[i];
            v = warp_sum(v);
        }
        if (lane == 0) s_res[warp] = v;
    }
    __syncthreads();                          // barrier #2 (s_res visible)

    // =============== phase 3: no-pass screen (exp-free) + coefficients =======
    const float Bmin = s_res[12], Bmax = s_res[13];
    int pass = 0;
    {
        float ubl = exp_ub(eln);
        float ubh = exp_ub(ehn);
        float lo = em - TGUARD * ubl;   // lower bound of true lo
        float hi = em + TGUARD * ubh;   // upper bound of true hi
        float cminj = Bmin * B * INV_S;
        float cmaxj = Bmax * B * INV_S;
        // NaN-safe: NaN comparisons are false -> pass=1 -> slow path
        if (!(cmaxj < lo) && !(cminj > hi)) pass = 1;
    }

    if (tid < 2 * NMOM) {
        const float invfact[NMOM] = {1.0f, 1.0f, 0.5f, 1.0f/6.0f, 1.0f/24.0f,
                                     1.0f/120.0f};
        int side = (tid >= NMOM) ? 1 : 0;
        int n    = tid - side * NMOM;
        s_cf[tid] = (n == 0) ? (float)KNOTS
                             : s_res[side * 5 + (n - 1)] * invfact[n];
        if (tid == 0) {
            float phi0 = -lower;
            float phiE = fmaf((float)(S_PTS - 1) * INV_SAMP, lower + upper, -lower);
            float tmax = fmaxf(phi0 * phi0, phiE * phiE);
            float gate = s_res[11] * tmax;
            s_fastenv = (gate <= GATE) ? 1 : 0;   // NaN -> slow env loop
        }
    }
    float R = (float)(KNOTS - 1) * s_res[10];      // Rbase
    // barrier #3: or-result + visibility of s_cf / s_fastenv
    const int slow = __syncthreads_or(pass) | anyvar;

    // ======================= SLOW PATH (general correctness) =================
    float* s_w    = pool;
    float* s_glow = pool + 1024;
    float* s_gd   = pool + 2048;
    float* s_grl  = pool + 3072;
    float* s_grh  = pool + 4096;
    float* s_cst  = pool + 5120;

    if (slow) {
        float* sA   = pool;
        float* sB   = pool + 1024;
        float* sV0c = pool + 2048;
        float* sSvj = pool + 3072;
        float* sCb  = pool + 4096;
        float* sEm  = pool + 5120;
        float* sErl = pool + 6144;
        float* sErh = pool + 7168;
        float* sCw  = pool + 8192;

        {
            float sp, cp;
            __sincosf(pol[tid], &sp, &cp);
            sA[tid]   = B;
            sB[tid]   = B;
            sV0c[tid] = v0c;
            sSvj[tid] = sp * v0c;
            sCb[tid]  = cp * B;
            sEm[tid]  = em;
            sErl[tid] = __expf(-eln);   // exact exp(-elow)
            sErh[tid] = __expf(-ehn);   // exact exp(-ehigh)
            sCw[tid]  = 0.0f;
        }
        __syncthreads();

        // non-constant knots: true A via S-loop; owning block stores smear rows
        if (anyvar) {
            for (int k = 0; k < KNOTS; k++) {
                float xkk = x[k];
                float xs  = ((upper - lower) * xkk) * INV_SAMP;
                if (xs == 0.0f) continue;
                float xl = (1.0f - lower) * xkk;
                float rl = __expf(-klow[k]);
                float rh = __expf(-khigh[k]);
                float mn = kmean[k];
                bool own = (bid == (k >> 8));    // 256 knots per owning block
                float* __restrict__ row = &g_smear[(size_t)k * S_PTS];
                float acc = 0.0f;
                for (int s = tid; s < S_PTS; s += NTHR) {
                    float gv = fmaf(xs, (float)s, xl);
                    float dd = gv - mn;
                    float rr = (gv <= mn) ? rl : rh;
                    float aa = dd * rr;
                    float vv = __expf(-0.5f * aa * aa);
                    if (own) row[s] = vv;
                    acc += vv;
                }
                float tot = block_sum_b(acc, red);
                if (tid == 0) sA[k] = tot;
                __syncthreads();
            }
        }

        // mix: 256 rows/block = 32 warps x 8 rows
        float rp = 0.0f;
        #pragma unroll
        for (int rr = 0; rr < 8; rr++) {
            int i = bid * 256 + rr * 32 + warp;
            float AiS  = sA[i] * INV_S;
            float Bi   = sB[i];
            float v0ci = sV0c[i];
            float rs = 0.0f, c1 = 0.0f;
            for (int j = lane; j < KNOTS; j += 32) {
                float corr = AiS * sA[j];
                float emj = sEm[j];
                float dd = corr - emj;
                float r  = (corr <= emj) ? sErl[j] : sErh[j];
                float a  = dd * r;
                float e  = 0.5f * a * a;
                if (e < 88.0f) {
                    float m = __expf(-e);
                    if (j == i) m = 0.0f;
                    float cb = sCb[j];
                    rs += m;
                    c1 += m * cb;
                    rp += m * (v0ci * (cb - 1.0f) + Bi * sSvj[j]);
                    float v = Bi * m;
                    if (v != 0.0f) atomicAdd(&sCw[j], v);
                }
            }
            rs = warp_sum(rs);
            c1 = warp_sum(c1);
            if (lane == 0) { g_rowsum[i] = rs; g_coef1[i] = c1; }
        }
        float rpt = block_sum_b(rp, red);
        if (tid == 0) g_Rp[bid] = rpt;
        __syncthreads();
        g_cwp[bid * KNOTS + tid] = sCw[tid];

        grid_barrier();

        #pragma unroll
        for (int p = 0; p < NBLK; p++) R += g_Rp[p];

        __syncthreads();
        {
            float cw = 0.0f;
            #pragma unroll
            for (int p = 0; p < NBLK; p++) cw += g_cwp[p * KNOTS + tid];
            float w = g_coef1[tid] + (float)(KNOTS - 1) - g_rowsum[tid]
                    + __sinf(pol[tid]) * cw;
            s_w[tid]    = w;
            s_cst[tid]  = cst ? 1.0f : 0.0f;
            s_glow[tid] = xlow;
            s_gd[tid]   = highs - xlow;
            s_grl[tid]  = erlw;
            s_grh[tid]  = erhg;
        }
        __syncthreads();
    } else if (!s_fastenv) {
        // fast path but envelope needs the exact per-knot loop
        __syncthreads();   // buf dead
        s_glow[tid] = xlow;
        s_gd[tid]   = highs - xlow;
        s_grl[tid]  = erlw;
        s_grh[tid]  = erhg;
        __syncthreads();
    }

    // ======================= output (1 sample / thread) ======================
    int s = bid * NTHR + tid;
    if (s >= S_PTS) return;

    float xi  = (float)s * INV_SAMP;
    float phi = fmaf(xi, lower + upper, -lower);
    float t   = phi * phi;

    float env;
    if (s_fastenv) {
        const float* cf = s_cf + ((phi <= 0.0f) ? 0 : NMOM);
        float u = -t;
        env = cf[NMOM - 1];
        #pragma unroll
        for (int n = NMOM - 2; n >= 0; n--) env = fmaf(env, u, cf[n]);
    } else {
        env = 0.0f;
        for (int k = 0; k < KNOTS; k++) {
            float mn = x[k];
            float gv = fmaf(s_gd[k], xi, s_glow[k]);
            float dd = gv - mn;
            float r  = (gv <= mn) ? s_grl[k] : s_grh[k];
            float a  = dd * r;
            env += __expf(-0.5f * a * a);
        }
    }

    float res = R;
    if (slow && anyvar) {
        for (int k = 0; k < KNOTS; k++) {
            if (s_cst[k] == 0.0f)
                res = fmaf(s_w[k], g_smear[(size_t)k * S_PTS + s], res);
        }
    }
    out[s] = env * res;
}

// ---------------- launch ------------------------------------------------------
extern "C" void kernel_launch(void* const* d_in, const int* in_sizes, int n_in,
                              void* d_out, int out_size) {
    const float* x     = (const float*)d_in[0];
    const float* sw    = (const float*)d_in[1];
    const float* kmean = (const float*)d_in[2];
    const float* klow  = (const float*)d_in[3];
    const float* khigh = (const float*)d_in[4];
    const float* emean = (const float*)d_in[5];
    const float* elow  = (const float*)d_in[6];
    const float* ehigh = (const float*)d_in[7];
    const float* pol   = (const float*)d_in[8];
    float* out = (float*)d_out;

    knot_one<<<NBLK, NTHR>>>(x, sw, kmean, klow, khigh, emean, elow, ehigh, pol, out);
}